// round 6
// baseline (speedup 1.0000x reference)
#include <cuda_runtime.h>

#define N_NODES 100000
#define N_EDGES 1600000
#define F_IN    128
#define F_HID   128
#define F_OUT   64

typedef unsigned long long u64;

// ---------------- packed f32x2 helpers (Blackwell double-rate fp32) ----------------
__device__ __forceinline__ u64 pack2(float lo, float hi) {
    u64 r; asm("mov.b64 %0, {%1, %2};" : "=l"(r) : "f"(lo), "f"(hi)); return r;
}
__device__ __forceinline__ void fma2(u64& d, u64 a, u64 b) {
    asm("fma.rn.f32x2 %0, %1, %2, %3;" : "=l"(d) : "l"(a), "l"(b), "l"(d));
}
__device__ __forceinline__ void unpack2(u64 v, float& lo, float& hi) {
    asm("mov.b64 {%0, %1}, %2;" : "=f"(lo), "=f"(hi) : "l"(v));
}

// ---------------- static device scratch ----------------
__device__ int   g_cnt[N_NODES];
__device__ int   g_off[N_NODES + 1];
__device__ int   g_cur[N_NODES];
__device__ int   g_srcs[N_EDGES];
__device__ float g_dinv[N_NODES];
__device__ __align__(16) float g_hs1 [N_NODES * F_HID];   // dinv-scaled x@W1
__device__ __align__(16) float g_agg1[N_NODES * F_HID];   // relu(layer1 out)
__device__ __align__(16) float g_hs2 [N_NODES * F_OUT];   // dinv-scaled agg1@W2

// ---------------- CSR build ----------------
__global__ void k_zero_cnt() {
    int i = blockIdx.x * blockDim.x + threadIdx.x;
    if (i < N_NODES) g_cnt[i] = 0;
}

// edge_index is int32 on device. 4 edges per thread via int4.
__global__ void k_hist(const int* __restrict__ ei) {
    int e4 = blockIdx.x * blockDim.x + threadIdx.x;
    if (e4 * 4 < N_EDGES) {
        int4 d = *(const int4*)&ei[N_EDGES + e4 * 4];
        if ((unsigned)d.x < N_NODES) atomicAdd(&g_cnt[d.x], 1);
        if ((unsigned)d.y < N_NODES) atomicAdd(&g_cnt[d.y], 1);
        if ((unsigned)d.z < N_NODES) atomicAdd(&g_cnt[d.z], 1);
        if ((unsigned)d.w < N_NODES) atomicAdd(&g_cnt[d.w], 1);
    }
}

// single-block scan + dinv + cursor init (merged to save a launch)
__global__ void k_scan_all() {
    __shared__ int sm[1024];
    const int t   = threadIdx.x;
    const int SEG = (N_NODES + 1023) / 1024;        // 98
    int s    = t * SEG;
    int epos = min(s + SEG, N_NODES);
    int sum = 0;
    for (int i = s; i < epos; i++) sum += g_cnt[i];
    sm[t] = sum;
    for (int d = 1; d < 1024; d <<= 1) {
        __syncthreads();
        int v = (t >= d) ? sm[t - d] : 0;
        __syncthreads();
        sm[t] += v;
    }
    __syncthreads();
    int run = sm[t] - sum;                           // exclusive prefix
    for (int i = s; i < epos; i++) {
        int c = g_cnt[i];
        g_off[i]  = run;
        g_cur[i]  = run;
        g_dinv[i] = rsqrtf((float)(c + 1));          // deg incl self-loop, >=1
        run += c;
    }
    if (t == 1023) g_off[N_NODES] = sm[1023];
}

__global__ void k_fill(const int* __restrict__ ei) {
    int e4 = blockIdx.x * blockDim.x + threadIdx.x;
    if (e4 * 4 < N_EDGES) {
        int4 s = *(const int4*)&ei[e4 * 4];
        int4 d = *(const int4*)&ei[N_EDGES + e4 * 4];
        if ((unsigned)d.x < N_NODES && (unsigned)s.x < N_NODES)
            g_srcs[atomicAdd(&g_cur[d.x], 1)] = s.x;
        if ((unsigned)d.y < N_NODES && (unsigned)s.y < N_NODES)
            g_srcs[atomicAdd(&g_cur[d.y], 1)] = s.y;
        if ((unsigned)d.z < N_NODES && (unsigned)s.z < N_NODES)
            g_srcs[atomicAdd(&g_cur[d.z], 1)] = s.z;
        if ((unsigned)d.w < N_NODES && (unsigned)s.w < N_NODES)
            g_srcs[atomicAdd(&g_cur[d.w], 1)] = s.w;
    }
}

// ---------- SGEMM body: double-buffered smem, packed f32x2 FMA, dinv epilogue ----------
template<int BM, int BN, int BK, int TM, int TN>
__device__ __forceinline__ void gemm_body(
    const float* __restrict__ A, const float* __restrict__ B,
    float* __restrict__ C, int K, int Nc)
{
    constexpr int TX  = BN / TN;
    constexpr int TY  = BM / TM;
    constexpr int NT  = TX * TY;
    constexpr int TN2 = TN / 2;
    __shared__ float As[2][BK][BM + 4];
    __shared__ __align__(16) float Bs[2][BK][BN];

    const int tid = threadIdx.x;
    const int tx  = tid % TX;
    const int ty  = tid / TX;
    const int rowBase = blockIdx.x * BM;

    auto load_tiles = [&](int kb, int buf) {
#pragma unroll
        for (int i = tid; i < BM * BK / 4; i += NT) {
            int r  = i / (BK / 4);
            int kq = (i % (BK / 4)) * 4;
            int gr = rowBase + r;
            float4 v = make_float4(0.f, 0.f, 0.f, 0.f);
            if (gr < N_NODES) v = *(const float4*)&A[gr * K + kb + kq];
            As[buf][kq + 0][r] = v.x; As[buf][kq + 1][r] = v.y;
            As[buf][kq + 2][r] = v.z; As[buf][kq + 3][r] = v.w;
        }
#pragma unroll
        for (int i = tid; i < BK * BN / 4; i += NT) {
            int k = (i * 4) / BN;
            int c = (i * 4) % BN;
            *(float4*)&Bs[buf][k][c] = *(const float4*)&B[(kb + k) * Nc + c];
        }
    };

    u64 acc2[TM][TN2];
#pragma unroll
    for (int i = 0; i < TM; i++)
#pragma unroll
        for (int j = 0; j < TN2; j++) acc2[i][j] = 0ull;

    load_tiles(0, 0);
    __syncthreads();

    int p = 0;
    for (int kb = 0; kb < K; kb += BK, p ^= 1) {
        if (kb + BK < K) load_tiles(kb + BK, p ^ 1);   // prefetch next tile
#pragma unroll
        for (int k = 0; k < BK; k++) {
            float a[TM];
#pragma unroll
            for (int i = 0; i < TM; i += 4)
                *(float4*)&a[i] = *(const float4*)&As[p][k][ty * TM + i];
            u64 aa[TM];
#pragma unroll
            for (int i = 0; i < TM; i++) aa[i] = pack2(a[i], a[i]);
            u64 bb[TN2];
#pragma unroll
            for (int j = 0; j < TN2; j++) bb[j] = *(const u64*)&Bs[p][k][tx * TN + 2 * j];
#pragma unroll
            for (int i = 0; i < TM; i++)
#pragma unroll
                for (int j = 0; j < TN2; j++) fma2(acc2[i][j], aa[i], bb[j]);
        }
        __syncthreads();
    }
#pragma unroll
    for (int i = 0; i < TM; i++) {
        int gr = rowBase + ty * TM + i;
        if (gr < N_NODES) {
            float dv = g_dinv[gr];
#pragma unroll
            for (int j = 0; j < TN2; j += 2) {
                float4 v;
                unpack2(acc2[i][j + 0], v.x, v.y);
                unpack2(acc2[i][j + 1], v.z, v.w);
                v.x *= dv; v.y *= dv; v.z *= dv; v.w *= dv;
                *(float4*)&C[gr * Nc + tx * TN + 2 * j] = v;
            }
        }
    }
}

// layer-1 GEMM: x @ W1 -> g_hs1 (dinv-scaled)
__global__ void k_gemm1(const float* __restrict__ x, const float* __restrict__ W1) {
    gemm_body<128, 128, 16, 8, 8>(x, W1, g_hs1, F_IN, F_HID);
}

// layer-2 GEMM: g_agg1 @ W2 -> g_hs2 (dinv-scaled)
__global__ void k_gemm2(const float* __restrict__ W2) {
    gemm_body<128, 64, 16, 8, 4>(g_agg1, W2, g_hs2, F_HID, F_OUT);
}

// ---------------- aggregation: warp per node, gather over CSR ----------------
// layer 1: width 128 (float4 per lane), +bias, relu
__global__ void k_agg1(const float* __restrict__ b1) {
    int w    = (blockIdx.x * blockDim.x + threadIdx.x) >> 5;
    int lane = threadIdx.x & 31;
    if (w >= N_NODES) return;
    const float4* hs = (const float4*)g_hs1;      // 32 float4 per row (pre-scaled)
    float4 acc = hs[w * 32 + lane];               // self-loop term
    int e  = g_off[w];
    int e1 = g_off[w + 1];
    for (; e + 7 < e1; e += 8) {
        int s[8];
#pragma unroll
        for (int q = 0; q < 8; q++) s[q] = g_srcs[e + q];
        float4 v[8];
#pragma unroll
        for (int q = 0; q < 8; q++) v[q] = hs[s[q] * 32 + lane];
#pragma unroll
        for (int q = 0; q < 8; q++) {
            acc.x += v[q].x; acc.y += v[q].y; acc.z += v[q].z; acc.w += v[q].w;
        }
    }
    for (; e < e1; e++) {
        int s = g_srcs[e];
        float4 v = hs[s * 32 + lane];
        acc.x += v.x; acc.y += v.y; acc.z += v.z; acc.w += v.w;
    }
    float dv = g_dinv[w];
    float4 bb = ((const float4*)b1)[lane];
    float4 o;
    o.x = fmaxf(fmaf(acc.x, dv, bb.x), 0.f);
    o.y = fmaxf(fmaf(acc.y, dv, bb.y), 0.f);
    o.z = fmaxf(fmaf(acc.z, dv, bb.z), 0.f);
    o.w = fmaxf(fmaf(acc.w, dv, bb.w), 0.f);
    ((float4*)g_agg1)[w * 32 + lane] = o;
}

// layer 2: width 64 (float2 per lane), +bias, no relu, writes d_out
__global__ void k_agg2(const float* __restrict__ b2, float* __restrict__ out) {
    int w    = (blockIdx.x * blockDim.x + threadIdx.x) >> 5;
    int lane = threadIdx.x & 31;
    if (w >= N_NODES) return;
    const float2* hs = (const float2*)g_hs2;      // 32 float2 per row (pre-scaled)
    float2 acc = hs[w * 32 + lane];               // self-loop term
    int e  = g_off[w];
    int e1 = g_off[w + 1];
    for (; e + 7 < e1; e += 8) {
        int s[8];
#pragma unroll
        for (int q = 0; q < 8; q++) s[q] = g_srcs[e + q];
        float2 v[8];
#pragma unroll
        for (int q = 0; q < 8; q++) v[q] = hs[s[q] * 32 + lane];
#pragma unroll
        for (int q = 0; q < 8; q++) { acc.x += v[q].x; acc.y += v[q].y; }
    }
    for (; e < e1; e++) {
        int s = g_srcs[e];
        float2 v = hs[s * 32 + lane];
        acc.x += v.x; acc.y += v.y;
    }
    float dv = g_dinv[w];
    float2 bb = ((const float2*)b2)[lane];
    float2 o;
    o.x = fmaf(acc.x, dv, bb.x);
    o.y = fmaf(acc.y, dv, bb.y);
    ((float2*)out)[w * 32 + lane] = o;
}

// ---------------- launcher (serial stream; gemm1 at submission index 3 for ncu) ----
extern "C" void kernel_launch(void* const* d_in, const int* in_sizes, int n_in,
                              void* d_out, int out_size) {
    const float* x  = (const float*)d_in[0];
    const int*   ei = (const int*)d_in[1];
    const float* W1 = (const float*)d_in[2];
    const float* b1 = (const float*)d_in[3];
    const float* W2 = (const float*)d_in[4];
    const float* b2 = (const float*)d_in[5];
    float* out = (float*)d_out;

    const int NB_N  = (N_NODES + 255) / 256;
    const int NB_E4 = (N_EDGES / 4 + 255) / 256;

    k_zero_cnt<<<NB_N, 256>>>();                            // 0
    k_hist    <<<NB_E4, 256>>>(ei);                         // 1
    k_scan_all<<<1, 1024>>>();                              // 2  (scan + dinv + cur)
    k_gemm1   <<<(N_NODES + 127) / 128, 256>>>(x, W1);      // 3  <- ncu capture slot
    k_fill    <<<NB_E4, 256>>>(ei);                         // 4
    k_agg1    <<<(N_NODES + 7) / 8, 256>>>(b1);             // 5
    k_gemm2   <<<(N_NODES + 127) / 128, 256>>>(W2);         // 6
    k_agg2    <<<(N_NODES + 7) / 8, 256>>>(b2, out);        // 7
}

// round 12
// speedup vs baseline: 1.0858x; 1.0858x over previous
#include <cuda_runtime.h>
#include <cuda_bf16.h>
#include <cstdint>

#define N_NODES 100000
#define N_EDGES 1600000
#define F_IN    128
#define F_HID   128
#define F_OUT   64

// ================= static device scratch =================
__device__ int   g_cnt[N_NODES];
__device__ int   g_off[N_NODES + 1];
__device__ int   g_cur[N_NODES];
__device__ int   g_srcs[N_EDGES];
__device__ float g_dinv[N_NODES];
__device__ __align__(16) float g_hs1 [N_NODES * F_HID];
__device__ __align__(16) float g_agg1[N_NODES * F_HID];
__device__ __align__(16) float g_hs2 [N_NODES * F_OUT];
// pre-split weights, K-major [n][k], bf16
__device__ __align__(16) __nv_bfloat16 g_W1hi[F_HID * F_IN];
__device__ __align__(16) __nv_bfloat16 g_W1lo[F_HID * F_IN];
__device__ __align__(16) __nv_bfloat16 g_W2hi[F_OUT * F_HID];
__device__ __align__(16) __nv_bfloat16 g_W2lo[F_OUT * F_HID];

// ================= helpers =================
__device__ __forceinline__ uint32_t packbf(__nv_bfloat16 a, __nv_bfloat16 b) {
    return ((uint32_t)__bfloat16_as_ushort(b) << 16) | __bfloat16_as_ushort(a);
}

__device__ __forceinline__ void mma_bf16(float* d, const uint32_t* a, const uint32_t* b) {
    asm volatile(
        "mma.sync.aligned.m16n8k16.row.col.f32.bf16.bf16.f32 "
        "{%0,%1,%2,%3}, {%4,%5,%6,%7}, {%8,%9}, {%0,%1,%2,%3};"
        : "+f"(d[0]), "+f"(d[1]), "+f"(d[2]), "+f"(d[3])
        : "r"(a[0]), "r"(a[1]), "r"(a[2]), "r"(a[3]), "r"(b[0]), "r"(b[1]));
}

// ================= init: zero histogram + split/transpose weights =================
#define INIT_W1 (F_HID * F_IN)      // 16384
#define INIT_W2 (F_OUT * F_HID)     // 8192
#define INIT_TOTAL (N_NODES + INIT_W1 + INIT_W2)

__global__ void k_init(const float* __restrict__ W1, const float* __restrict__ W2) {
    int i = blockIdx.x * blockDim.x + threadIdx.x;
    if (i < N_NODES) { g_cnt[i] = 0; return; }
    int e = i - N_NODES;
    if (e < INIT_W1) {                     // W1: [k=128][n=128] -> [n][k]
        int n = e >> 7, k = e & 127;
        float v = W1[k * F_HID + n];
        __nv_bfloat16 h = __float2bfloat16(v);
        g_W1hi[e] = h;
        g_W1lo[e] = __float2bfloat16(v - __bfloat162float(h));
        return;
    }
    e -= INIT_W1;
    if (e < INIT_W2) {                     // W2: [k=128][n=64] -> [n][k]
        int n = e >> 7, k = e & 127;
        float v = W2[k * F_OUT + n];
        __nv_bfloat16 h = __float2bfloat16(v);
        g_W2hi[e] = h;
        g_W2lo[e] = __float2bfloat16(v - __bfloat162float(h));
    }
}

// ================= CSR build =================
__global__ void k_hist(const int* __restrict__ ei) {
    int e4 = blockIdx.x * blockDim.x + threadIdx.x;
    if (e4 * 4 < N_EDGES) {
        int4 d = *(const int4*)&ei[N_EDGES + e4 * 4];
        if ((unsigned)d.x < N_NODES) atomicAdd(&g_cnt[d.x], 1);
        if ((unsigned)d.y < N_NODES) atomicAdd(&g_cnt[d.y], 1);
        if ((unsigned)d.z < N_NODES) atomicAdd(&g_cnt[d.z], 1);
        if ((unsigned)d.w < N_NODES) atomicAdd(&g_cnt[d.w], 1);
    }
}

__global__ void k_scan_all() {
    __shared__ int sm[1024];
    const int t = threadIdx.x;
    const int SEG = (N_NODES + 1023) / 1024;
    int s = t * SEG;
    int epos = min(s + SEG, N_NODES);
    int sum = 0;
    for (int i = s; i < epos; i++) sum += g_cnt[i];
    sm[t] = sum;
    for (int d = 1; d < 1024; d <<= 1) {
        __syncthreads();
        int v = (t >= d) ? sm[t - d] : 0;
        __syncthreads();
        sm[t] += v;
    }
    __syncthreads();
    int run = sm[t] - sum;
    for (int i = s; i < epos; i++) {
        int c = g_cnt[i];
        g_off[i]  = run;
        g_cur[i]  = run;
        g_dinv[i] = rsqrtf((float)(c + 1));
        run += c;
    }
    if (t == 1023) g_off[N_NODES] = sm[1023];
}

__global__ void k_fill(const int* __restrict__ ei) {
    int e4 = blockIdx.x * blockDim.x + threadIdx.x;
    if (e4 * 4 < N_EDGES) {
        int4 s = *(const int4*)&ei[e4 * 4];
        int4 d = *(const int4*)&ei[N_EDGES + e4 * 4];
        if ((unsigned)d.x < N_NODES && (unsigned)s.x < N_NODES)
            g_srcs[atomicAdd(&g_cur[d.x], 1)] = s.x;
        if ((unsigned)d.y < N_NODES && (unsigned)s.y < N_NODES)
            g_srcs[atomicAdd(&g_cur[d.y], 1)] = s.y;
        if ((unsigned)d.z < N_NODES && (unsigned)s.z < N_NODES)
            g_srcs[atomicAdd(&g_cur[d.z], 1)] = s.z;
        if ((unsigned)d.w < N_NODES && (unsigned)s.w < N_NODES)
            g_srcs[atomicAdd(&g_cur[d.w], 1)] = s.w;
    }
}

// ================= split-bf16 GEMM via mma.sync (HMMA) =================
// D[m,n] = A[m,:]@W[:,n] ~= Ahi@Whi + Ahi@Wlo + Alo@Whi, fp32 accum; epilogue *dinv[m].
// CTA: 256 thr (8 warps), tile 128 x NW; warp tile 64 x (NW/4); K=128, chunks of 32.
// NOTE: called from __global__ wrappers that reference device globals in DEVICE code.
template<int NW>
__device__ __forceinline__ void mma_body(
    const float* __restrict__ A,
    const __nv_bfloat16* __restrict__ Whi,
    const __nv_bfloat16* __restrict__ Wlo,
    float* __restrict__ C)
{
    constexpr int K  = 128;
    constexpr int KC = 32;
    constexpr int SA = KC + 8;        // A smem stride (elems)
    constexpr int SW = K + 8;         // W smem stride (elems)
    constexpr int WN = NW / 4;        // warp n extent (32 or 16)
    constexpr int NF = WN / 8;        // n-frags per warp (4 or 2)
    constexpr int OFF_AH = 0;
    constexpr int OFF_AL = 128 * SA * 2;          // 10240
    constexpr int OFF_WH = 2 * 128 * SA * 2;      // 20480
    constexpr int OFF_WL = OFF_WH + NW * SW * 2;

    extern __shared__ __align__(16) char sm[];
    const int tid  = threadIdx.x;
    const int wid  = tid >> 5;
    const int lane = tid & 31;
    const int mw   = wid >> 2;        // 0..1
    const int nw   = wid & 3;         // 0..3
    const int rowBase = blockIdx.x * 128;

    // ---- full W (hi/lo) into smem, [n][k] with stride SW ----
    for (int i = tid; i < NW * (K / 2); i += 256) {
        int n = i / (K / 2), k2 = i % (K / 2);
        uint32_t wh = ((const uint32_t*)Whi)[n * (K / 2) + k2];
        uint32_t wl = ((const uint32_t*)Wlo)[n * (K / 2) + k2];
        *(uint32_t*)(sm + OFF_WH + (n * SW + 2 * k2) * 2) = wh;
        *(uint32_t*)(sm + OFF_WL + (n * SW + 2 * k2) * 2) = wl;
    }

    float acc[4][NF][4];
#pragma unroll
    for (int mf = 0; mf < 4; mf++)
#pragma unroll
        for (int nf = 0; nf < NF; nf++)
#pragma unroll
            for (int j = 0; j < 4; j++) acc[mf][nf][j] = 0.f;

    const int arow  = tid >> 1;       // 0..127
    const int ahalf = tid & 1;        // k sub-half (16 elems)
    const int grow  = rowBase + arow;
    const bool aok  = grow < N_NODES;

    for (int kc = 0; kc < K; kc += KC) {
        // ---- convert A chunk fp32 -> bf16 hi/lo into smem ----
        {
            const float4* src = (const float4*)&A[(size_t)(aok ? grow : 0) * K + kc + ahalf * 16];
#pragma unroll
            for (int i = 0; i < 4; i++) {
                float4 v = aok ? src[i] : make_float4(0.f, 0.f, 0.f, 0.f);
                __nv_bfloat16 hx = __float2bfloat16(v.x), hy = __float2bfloat16(v.y);
                __nv_bfloat16 hz = __float2bfloat16(v.z), hw = __float2bfloat16(v.w);
                uint32_t h0 = packbf(hx, hy), h1 = packbf(hz, hw);
                uint32_t l0 = packbf(__float2bfloat16(v.x - __bfloat162float(hx)),
                                     __float2bfloat16(v.y - __bfloat162float(hy)));
                uint32_t l1 = packbf(__float2bfloat16(v.z - __bfloat162float(hz)),
                                     __float2bfloat16(v.w - __bfloat162float(hw)));
                int col = ahalf * 16 + i * 4;
                *(uint32_t*)(sm + OFF_AH + (arow * SA + col) * 2)     = h0;
                *(uint32_t*)(sm + OFF_AH + (arow * SA + col + 2) * 2) = h1;
                *(uint32_t*)(sm + OFF_AL + (arow * SA + col) * 2)     = l0;
                *(uint32_t*)(sm + OFF_AL + (arow * SA + col + 2) * 2) = l1;
            }
        }
        __syncthreads();

#pragma unroll
        for (int ks = 0; ks < KC / 16; ks++) {
            const int k0 = ks * 16;
            uint32_t bh[NF][2], bl[NF][2];
#pragma unroll
            for (int nf = 0; nf < NF; nf++) {
                int n0 = nw * WN + nf * 8 + (lane >> 2);
                int bc = kc + k0 + (lane & 3) * 2;
                bh[nf][0] = *(const uint32_t*)(sm + OFF_WH + (n0 * SW + bc) * 2);
                bh[nf][1] = *(const uint32_t*)(sm + OFF_WH + (n0 * SW + bc + 8) * 2);
                bl[nf][0] = *(const uint32_t*)(sm + OFF_WL + (n0 * SW + bc) * 2);
                bl[nf][1] = *(const uint32_t*)(sm + OFF_WL + (n0 * SW + bc + 8) * 2);
            }
#pragma unroll
            for (int mf = 0; mf < 4; mf++) {
                int r0 = mw * 64 + mf * 16 + (lane >> 2);
                int ac = k0 + (lane & 3) * 2;
                uint32_t ah[4], al[4];
                ah[0] = *(const uint32_t*)(sm + OFF_AH + ((r0)     * SA + ac) * 2);
                ah[1] = *(const uint32_t*)(sm + OFF_AH + ((r0 + 8) * SA + ac) * 2);
                ah[2] = *(const uint32_t*)(sm + OFF_AH + ((r0)     * SA + ac + 8) * 2);
                ah[3] = *(const uint32_t*)(sm + OFF_AH + ((r0 + 8) * SA + ac + 8) * 2);
                al[0] = *(const uint32_t*)(sm + OFF_AL + ((r0)     * SA + ac) * 2);
                al[1] = *(const uint32_t*)(sm + OFF_AL + ((r0 + 8) * SA + ac) * 2);
                al[2] = *(const uint32_t*)(sm + OFF_AL + ((r0)     * SA + ac + 8) * 2);
                al[3] = *(const uint32_t*)(sm + OFF_AL + ((r0 + 8) * SA + ac + 8) * 2);
#pragma unroll
                for (int nf = 0; nf < NF; nf++) {
                    mma_bf16(acc[mf][nf], ah, bh[nf]);
                    mma_bf16(acc[mf][nf], ah, bl[nf]);
                    mma_bf16(acc[mf][nf], al, bh[nf]);
                }
            }
        }
        __syncthreads();
    }

    // ---- epilogue: *dinv[row], fp32 store ----
#pragma unroll
    for (int mf = 0; mf < 4; mf++) {
        int r0 = rowBase + mw * 64 + mf * 16 + (lane >> 2);
        int r1 = r0 + 8;
        float dv0 = (r0 < N_NODES) ? g_dinv[r0] : 0.f;
        float dv1 = (r1 < N_NODES) ? g_dinv[r1] : 0.f;
#pragma unroll
        for (int nf = 0; nf < NF; nf++) {
            int col = nw * WN + nf * 8 + (lane & 3) * 2;
            if (r0 < N_NODES) {
                float2 v = make_float2(acc[mf][nf][0] * dv0, acc[mf][nf][1] * dv0);
                *(float2*)&C[(size_t)r0 * NW + col] = v;
            }
            if (r1 < N_NODES) {
                float2 v = make_float2(acc[mf][nf][2] * dv1, acc[mf][nf][3] * dv1);
                *(float2*)&C[(size_t)r1 * NW + col] = v;
            }
        }
    }
}

// wrappers: device globals referenced in DEVICE code (host passing is illegal)
__global__ __launch_bounds__(256) void k_mma1(const float* __restrict__ x) {
    mma_body<F_HID>(x, g_W1hi, g_W1lo, g_hs1);
}
__global__ __launch_bounds__(256) void k_mma2() {
    mma_body<F_OUT>(g_agg1, g_W2hi, g_W2lo, g_hs2);
}

static constexpr int SMEM_G1 = 20480 + 2 * (F_HID * (F_IN + 8) * 2);   // 90112
static constexpr int SMEM_G2 = 20480 + 2 * (F_OUT * (F_HID + 8) * 2);  // 55296

struct HxAttr {
    HxAttr() {
        cudaFuncSetAttribute(k_mma1, cudaFuncAttributeMaxDynamicSharedMemorySize, SMEM_G1);
        cudaFuncSetAttribute(k_mma2, cudaFuncAttributeMaxDynamicSharedMemorySize, SMEM_G2);
    }
};
static HxAttr g_attr;

// ================= aggregation: warp per node, gather over CSR =================
__global__ void k_agg1(const float* __restrict__ b1) {
    int w    = (blockIdx.x * blockDim.x + threadIdx.x) >> 5;
    int lane = threadIdx.x & 31;
    if (w >= N_NODES) return;
    const float4* hs = (const float4*)g_hs1;
    float4 acc = hs[w * 32 + lane];
    int e  = g_off[w];
    int e1 = g_off[w + 1];
    for (; e + 7 < e1; e += 8) {
        int s[8];
#pragma unroll
        for (int q = 0; q < 8; q++) s[q] = g_srcs[e + q];
        float4 v[8];
#pragma unroll
        for (int q = 0; q < 8; q++) v[q] = hs[s[q] * 32 + lane];
#pragma unroll
        for (int q = 0; q < 8; q++) {
            acc.x += v[q].x; acc.y += v[q].y; acc.z += v[q].z; acc.w += v[q].w;
        }
    }
    for (; e < e1; e++) {
        int s = g_srcs[e];
        float4 v = hs[s * 32 + lane];
        acc.x += v.x; acc.y += v.y; acc.z += v.z; acc.w += v.w;
    }
    float dv = g_dinv[w];
    float4 bb = ((const float4*)b1)[lane];
    float4 o;
    o.x = fmaxf(fmaf(acc.x, dv, bb.x), 0.f);
    o.y = fmaxf(fmaf(acc.y, dv, bb.y), 0.f);
    o.z = fmaxf(fmaf(acc.z, dv, bb.z), 0.f);
    o.w = fmaxf(fmaf(acc.w, dv, bb.w), 0.f);
    ((float4*)g_agg1)[w * 32 + lane] = o;
}

__global__ void k_agg2(const float* __restrict__ b2, float* __restrict__ out) {
    int w    = (blockIdx.x * blockDim.x + threadIdx.x) >> 5;
    int lane = threadIdx.x & 31;
    if (w >= N_NODES) return;
    const float2* hs = (const float2*)g_hs2;
    float2 acc = hs[w * 32 + lane];
    int e  = g_off[w];
    int e1 = g_off[w + 1];
    for (; e + 7 < e1; e += 8) {
        int s[8];
#pragma unroll
        for (int q = 0; q < 8; q++) s[q] = g_srcs[e + q];
        float2 v[8];
#pragma unroll
        for (int q = 0; q < 8; q++) v[q] = hs[s[q] * 32 + lane];
#pragma unroll
        for (int q = 0; q < 8; q++) { acc.x += v[q].x; acc.y += v[q].y; }
    }
    for (; e < e1; e++) {
        int s = g_srcs[e];
        float2 v = hs[s * 32 + lane];
        acc.x += v.x; acc.y += v.y;
    }
    float dv = g_dinv[w];
    float2 bb = ((const float2*)b2)[lane];
    float2 o;
    o.x = fmaf(acc.x, dv, bb.x);
    o.y = fmaf(acc.y, dv, bb.y);
    ((float2*)out)[w * 32 + lane] = o;
}

// ================= launcher (k_mma1 at submission index 3 for ncu) =================
extern "C" void kernel_launch(void* const* d_in, const int* in_sizes, int n_in,
                              void* d_out, int out_size) {
    const float* x  = (const float*)d_in[0];
    const int*   ei = (const int*)d_in[1];
    const float* W1 = (const float*)d_in[2];
    const float* b1 = (const float*)d_in[3];
    const float* W2 = (const float*)d_in[4];
    const float* b2 = (const float*)d_in[5];
    float* out = (float*)d_out;

    const int NB_E4 = (N_EDGES / 4 + 255) / 256;
    const int NB_G  = (N_NODES + 127) / 128;   // 782

    k_init     <<<(INIT_TOTAL + 255) / 256, 256>>>(W1, W2);   // 0
    k_hist     <<<NB_E4, 256>>>(ei);                          // 1
    k_scan_all <<<1, 1024>>>();                               // 2
    k_mma1     <<<NB_G, 256, SMEM_G1>>>(x);                   // 3 <- ncu slot
    k_fill     <<<NB_E4, 256>>>(ei);                          // 4
    k_agg1     <<<(N_NODES + 7) / 8, 256>>>(b1);              // 5
    k_mma2     <<<NB_G, 256, SMEM_G2>>>();                    // 6
    k_agg2     <<<(N_NODES + 7) / 8, 256>>>(b2, out);         // 7
}

// round 14
// speedup vs baseline: 1.1283x; 1.0391x over previous
#include <cuda_runtime.h>
#include <cuda_bf16.h>
#include <cuda_fp16.h>
#include <cstdint>

#define N_NODES 100000
#define N_EDGES 1600000
#define F_IN    128
#define F_HID   128
#define F_OUT   64

typedef unsigned long long u64;

// ---------------- packed f32x2 helpers ----------------
__device__ __forceinline__ u64 pack2(float lo, float hi) {
    u64 r; asm("mov.b64 %0, {%1, %2};" : "=l"(r) : "f"(lo), "f"(hi)); return r;
}
__device__ __forceinline__ void fma2(u64& d, u64 a, u64 b) {
    asm("fma.rn.f32x2 %0, %1, %2, %3;" : "=l"(d) : "l"(a), "l"(b), "l"(d));
}
__device__ __forceinline__ void unpack2(u64 v, float& lo, float& hi) {
    asm("mov.b64 {%0, %1}, %2;" : "=f"(lo), "=f"(hi) : "l"(v));
}
__device__ __forceinline__ uint32_t packbf(__nv_bfloat16 a, __nv_bfloat16 b) {
    return ((uint32_t)__bfloat16_as_ushort(b) << 16) | __bfloat16_as_ushort(a);
}
__device__ __forceinline__ void mma_bf16(float* d, const uint32_t* a, const uint32_t* b) {
    asm volatile(
        "mma.sync.aligned.m16n8k16.row.col.f32.bf16.bf16.f32 "
        "{%0,%1,%2,%3}, {%4,%5,%6,%7}, {%8,%9}, {%0,%1,%2,%3};"
        : "+f"(d[0]), "+f"(d[1]), "+f"(d[2]), "+f"(d[3])
        : "r"(a[0]), "r"(a[1]), "r"(a[2]), "r"(a[3]), "r"(b[0]), "r"(b[1]));
}

// ---------------- static device scratch ----------------
__device__ int   g_cnt[N_NODES];
__device__ int   g_off[N_NODES + 1];
__device__ int   g_cur[N_NODES];
__device__ int   g_srcs[N_EDGES];
__device__ float g_dinv[N_NODES];
__device__ __align__(16) __half g_hs1h[N_NODES * F_HID];   // fp16 dinv-scaled x@W1
__device__ __align__(16) float  g_agg1[N_NODES * F_HID];   // relu(layer1 out), fp32
__device__ __align__(16) float  g_hs2 [N_NODES * F_OUT];   // dinv-scaled agg1@W2, fp32
// pre-split W1, K-major [n][k], bf16
__device__ __align__(16) __nv_bfloat16 g_W1hi[F_HID * F_IN];
__device__ __align__(16) __nv_bfloat16 g_W1lo[F_HID * F_IN];

// ---------------- init: zero histogram + split/transpose W1 ----------------
#define INIT_W1 (F_HID * F_IN)      // 16384
#define INIT_TOTAL (N_NODES + INIT_W1)

__global__ void k_init(const float* __restrict__ W1) {
    int i = blockIdx.x * blockDim.x + threadIdx.x;
    if (i < N_NODES) { g_cnt[i] = 0; return; }
    int e = i - N_NODES;
    if (e < INIT_W1) {                     // W1: [k=128][n=128] -> [n][k]
        int n = e >> 7, k = e & 127;
        float v = W1[k * F_HID + n];
        __nv_bfloat16 h = __float2bfloat16(v);
        g_W1hi[e] = h;
        g_W1lo[e] = __float2bfloat16(v - __bfloat162float(h));
    }
}

// ---------------- CSR build ----------------
__global__ void k_hist(const int* __restrict__ ei) {
    int e4 = blockIdx.x * blockDim.x + threadIdx.x;
    if (e4 * 4 < N_EDGES) {
        int4 d = *(const int4*)&ei[N_EDGES + e4 * 4];
        if ((unsigned)d.x < N_NODES) atomicAdd(&g_cnt[d.x], 1);
        if ((unsigned)d.y < N_NODES) atomicAdd(&g_cnt[d.y], 1);
        if ((unsigned)d.z < N_NODES) atomicAdd(&g_cnt[d.z], 1);
        if ((unsigned)d.w < N_NODES) atomicAdd(&g_cnt[d.w], 1);
    }
}

__global__ void k_scan_all() {
    __shared__ int sm[1024];
    const int t = threadIdx.x;
    const int SEG = (N_NODES + 1023) / 1024;
    int s = t * SEG;
    int epos = min(s + SEG, N_NODES);
    int sum = 0;
    for (int i = s; i < epos; i++) sum += g_cnt[i];
    sm[t] = sum;
    for (int d = 1; d < 1024; d <<= 1) {
        __syncthreads();
        int v = (t >= d) ? sm[t - d] : 0;
        __syncthreads();
        sm[t] += v;
    }
    __syncthreads();
    int run = sm[t] - sum;
    for (int i = s; i < epos; i++) {
        int c = g_cnt[i];
        g_off[i]  = run;
        g_cur[i]  = run;
        g_dinv[i] = rsqrtf((float)(c + 1));
        run += c;
    }
    if (t == 1023) g_off[N_NODES] = sm[1023];
}

__global__ void k_fill(const int* __restrict__ ei) {
    int e4 = blockIdx.x * blockDim.x + threadIdx.x;
    if (e4 * 4 < N_EDGES) {
        int4 s = *(const int4*)&ei[e4 * 4];
        int4 d = *(const int4*)&ei[N_EDGES + e4 * 4];
        if ((unsigned)d.x < N_NODES && (unsigned)s.x < N_NODES)
            g_srcs[atomicAdd(&g_cur[d.x], 1)] = s.x;
        if ((unsigned)d.y < N_NODES && (unsigned)s.y < N_NODES)
            g_srcs[atomicAdd(&g_cur[d.y], 1)] = s.y;
        if ((unsigned)d.z < N_NODES && (unsigned)s.z < N_NODES)
            g_srcs[atomicAdd(&g_cur[d.z], 1)] = s.z;
        if ((unsigned)d.w < N_NODES && (unsigned)s.w < N_NODES)
            g_srcs[atomicAdd(&g_cur[d.w], 1)] = s.w;
    }
}

// ================= layer-1 GEMM: split-bf16 mma.sync, fp16 output =================
// hs1h[m,n] = dinv[m] * (x[m,:]@W1[:,n]) in fp16.
// CTA: 256 thr (8 warps), tile 128 x 128; warp tile 64 x 32; K=128, chunks of 32.
__global__ __launch_bounds__(256) void k_mma1(const float* __restrict__ A) {
    constexpr int NW = F_HID;
    constexpr int K  = 128;
    constexpr int KC = 32;
    constexpr int SA = KC + 8;
    constexpr int SW = K + 8;
    constexpr int WN = NW / 4;        // 32
    constexpr int NF = WN / 8;        // 4
    constexpr int OFF_AH = 0;
    constexpr int OFF_AL = 128 * SA * 2;
    constexpr int OFF_WH = 2 * 128 * SA * 2;
    constexpr int OFF_WL = OFF_WH + NW * SW * 2;

    extern __shared__ __align__(16) char sm[];
    const int tid  = threadIdx.x;
    const int wid  = tid >> 5;
    const int lane = tid & 31;
    const int mw   = wid >> 2;
    const int nw   = wid & 3;
    const int rowBase = blockIdx.x * 128;

    for (int i = tid; i < NW * (K / 2); i += 256) {
        int n = i / (K / 2), k2 = i % (K / 2);
        uint32_t wh = ((const uint32_t*)g_W1hi)[n * (K / 2) + k2];
        uint32_t wl = ((const uint32_t*)g_W1lo)[n * (K / 2) + k2];
        *(uint32_t*)(sm + OFF_WH + (n * SW + 2 * k2) * 2) = wh;
        *(uint32_t*)(sm + OFF_WL + (n * SW + 2 * k2) * 2) = wl;
    }

    float acc[4][NF][4];
#pragma unroll
    for (int mf = 0; mf < 4; mf++)
#pragma unroll
        for (int nf = 0; nf < NF; nf++)
#pragma unroll
            for (int j = 0; j < 4; j++) acc[mf][nf][j] = 0.f;

    const int arow  = tid >> 1;
    const int ahalf = tid & 1;
    const int grow  = rowBase + arow;
    const bool aok  = grow < N_NODES;

    for (int kc = 0; kc < K; kc += KC) {
        {
            const float4* src = (const float4*)&A[(size_t)(aok ? grow : 0) * K + kc + ahalf * 16];
#pragma unroll
            for (int i = 0; i < 4; i++) {
                float4 v = aok ? src[i] : make_float4(0.f, 0.f, 0.f, 0.f);
                __nv_bfloat16 hx = __float2bfloat16(v.x), hy = __float2bfloat16(v.y);
                __nv_bfloat16 hz = __float2bfloat16(v.z), hw = __float2bfloat16(v.w);
                uint32_t h0 = packbf(hx, hy), h1 = packbf(hz, hw);
                uint32_t l0 = packbf(__float2bfloat16(v.x - __bfloat162float(hx)),
                                     __float2bfloat16(v.y - __bfloat162float(hy)));
                uint32_t l1 = packbf(__float2bfloat16(v.z - __bfloat162float(hz)),
                                     __float2bfloat16(v.w - __bfloat162float(hw)));
                int col = ahalf * 16 + i * 4;
                *(uint32_t*)(sm + OFF_AH + (arow * SA + col) * 2)     = h0;
                *(uint32_t*)(sm + OFF_AH + (arow * SA + col + 2) * 2) = h1;
                *(uint32_t*)(sm + OFF_AL + (arow * SA + col) * 2)     = l0;
                *(uint32_t*)(sm + OFF_AL + (arow * SA + col + 2) * 2) = l1;
            }
        }
        __syncthreads();

#pragma unroll
        for (int ks = 0; ks < KC / 16; ks++) {
            const int k0 = ks * 16;
            uint32_t bh[NF][2], bl[NF][2];
#pragma unroll
            for (int nf = 0; nf < NF; nf++) {
                int n0 = nw * WN + nf * 8 + (lane >> 2);
                int bc = kc + k0 + (lane & 3) * 2;
                bh[nf][0] = *(const uint32_t*)(sm + OFF_WH + (n0 * SW + bc) * 2);
                bh[nf][1] = *(const uint32_t*)(sm + OFF_WH + (n0 * SW + bc + 8) * 2);
                bl[nf][0] = *(const uint32_t*)(sm + OFF_WL + (n0 * SW + bc) * 2);
                bl[nf][1] = *(const uint32_t*)(sm + OFF_WL + (n0 * SW + bc + 8) * 2);
            }
#pragma unroll
            for (int mf = 0; mf < 4; mf++) {
                int r0 = mw * 64 + mf * 16 + (lane >> 2);
                int ac = k0 + (lane & 3) * 2;
                uint32_t ah[4], al[4];
                ah[0] = *(const uint32_t*)(sm + OFF_AH + ((r0)     * SA + ac) * 2);
                ah[1] = *(const uint32_t*)(sm + OFF_AH + ((r0 + 8) * SA + ac) * 2);
                ah[2] = *(const uint32_t*)(sm + OFF_AH + ((r0)     * SA + ac + 8) * 2);
                ah[3] = *(const uint32_t*)(sm + OFF_AH + ((r0 + 8) * SA + ac + 8) * 2);
                al[0] = *(const uint32_t*)(sm + OFF_AL + ((r0)     * SA + ac) * 2);
                al[1] = *(const uint32_t*)(sm + OFF_AL + ((r0 + 8) * SA + ac) * 2);
                al[2] = *(const uint32_t*)(sm + OFF_AL + ((r0)     * SA + ac + 8) * 2);
                al[3] = *(const uint32_t*)(sm + OFF_AL + ((r0 + 8) * SA + ac + 8) * 2);
#pragma unroll
                for (int nf = 0; nf < NF; nf++) {
                    mma_bf16(acc[mf][nf], ah, bh[nf]);
                    mma_bf16(acc[mf][nf], ah, bl[nf]);
                    mma_bf16(acc[mf][nf], al, bh[nf]);
                }
            }
        }
        __syncthreads();
    }

    // epilogue: *dinv[row], convert fp16, store
#pragma unroll
    for (int mf = 0; mf < 4; mf++) {
        int r0 = rowBase + mw * 64 + mf * 16 + (lane >> 2);
        int r1 = r0 + 8;
        float dv0 = (r0 < N_NODES) ? g_dinv[r0] : 0.f;
        float dv1 = (r1 < N_NODES) ? g_dinv[r1] : 0.f;
#pragma unroll
        for (int nf = 0; nf < NF; nf++) {
            int col = nw * WN + nf * 8 + (lane & 3) * 2;
            if (r0 < N_NODES)
                *(__half2*)&g_hs1h[(size_t)r0 * NW + col] =
                    __floats2half2_rn(acc[mf][nf][0] * dv0, acc[mf][nf][1] * dv0);
            if (r1 < N_NODES)
                *(__half2*)&g_hs1h[(size_t)r1 * NW + col] =
                    __floats2half2_rn(acc[mf][nf][2] * dv1, acc[mf][nf][3] * dv1);
        }
    }
}

static constexpr int SMEM_G1 = 2 * (128 * 40 * 2) + 2 * (F_HID * 136 * 2);   // 90112

struct HxAttr {
    HxAttr() {
        cudaFuncSetAttribute(k_mma1, cudaFuncAttributeMaxDynamicSharedMemorySize, SMEM_G1);
    }
};
static HxAttr g_attr;

// ================= layer-2 GEMM: R4-proven scalar FFMA2, dinv epilogue =================
// hs2[r,:] = dinv[r] * (agg1[r,:]@W2);  BM=128 BN=64 BK=16 TM=8 TN=4
__global__ void k_gemm2(const float* __restrict__ B) {
    constexpr int BM = 128, BN = 64, BK = 16, TM = 8, TN = 4;
    constexpr int TX  = BN / TN;      // 16
    constexpr int TY  = BM / TM;      // 16
    constexpr int NT  = TX * TY;      // 256
    constexpr int TN2 = TN / 2;
    const float* A = g_agg1;
    float* C = g_hs2;
    const int K = F_HID, Nc = F_OUT;
    __shared__ float As[BK][BM + 4];
    __shared__ __align__(16) float Bs[BK][BN];

    const int tid = threadIdx.x;
    const int tx  = tid % TX;
    const int ty  = tid / TX;
    const int rowBase = blockIdx.x * BM;

    u64 acc2[TM][TN2];
#pragma unroll
    for (int i = 0; i < TM; i++)
#pragma unroll
        for (int j = 0; j < TN2; j++) acc2[i][j] = 0ull;

    for (int kb = 0; kb < K; kb += BK) {
#pragma unroll
        for (int i = tid; i < BM * BK / 4; i += NT) {
            int r  = i / (BK / 4);
            int kq = (i % (BK / 4)) * 4;
            int gr = rowBase + r;
            float4 v = make_float4(0.f, 0.f, 0.f, 0.f);
            if (gr < N_NODES) v = *(const float4*)&A[gr * K + kb + kq];
            As[kq + 0][r] = v.x; As[kq + 1][r] = v.y;
            As[kq + 2][r] = v.z; As[kq + 3][r] = v.w;
        }
#pragma unroll
        for (int i = tid; i < BK * BN / 4; i += NT) {
            int k = (i * 4) / BN;
            int c = (i * 4) % BN;
            *(float4*)&Bs[k][c] = *(const float4*)&B[(kb + k) * Nc + c];
        }
        __syncthreads();
#pragma unroll
        for (int k = 0; k < BK; k++) {
            float a[TM];
#pragma unroll
            for (int i = 0; i < TM; i += 4) *(float4*)&a[i] = *(const float4*)&As[k][ty * TM + i];
            u64 aa[TM];
#pragma unroll
            for (int i = 0; i < TM; i++) aa[i] = pack2(a[i], a[i]);
            u64 bb[TN2];
#pragma unroll
            for (int j = 0; j < TN2; j++) bb[j] = *(const u64*)&Bs[k][tx * TN + 2 * j];
#pragma unroll
            for (int i = 0; i < TM; i++)
#pragma unroll
                for (int j = 0; j < TN2; j++) fma2(acc2[i][j], aa[i], bb[j]);
        }
        __syncthreads();
    }
#pragma unroll
    for (int i = 0; i < TM; i++) {
        int gr = rowBase + ty * TM + i;
        if (gr < N_NODES) {
            float dv = g_dinv[gr];
            float4 v;
            unpack2(acc2[i][0], v.x, v.y);
            unpack2(acc2[i][1], v.z, v.w);
            v.x *= dv; v.y *= dv; v.z *= dv; v.w *= dv;
            *(float4*)&C[gr * Nc + tx * TN] = v;
        }
    }
}

// ================= aggregation =================
// layer 1: fp16 table, 4 cols per lane (8B gather), fp32 accum, +bias, relu, fp32 out
__global__ void k_agg1(const float* __restrict__ b1) {
    int w    = (blockIdx.x * blockDim.x + threadIdx.x) >> 5;
    int lane = threadIdx.x & 31;
    if (w >= N_NODES) return;
    const uint2* hs = (const uint2*)g_hs1h;      // 32 x 8B per row
    float4 acc;
    {
        uint2 u = hs[(size_t)w * 32 + lane];     // self-loop
        float2 f0 = __half22float2(*(__half2*)&u.x);
        float2 f1 = __half22float2(*(__half2*)&u.y);
        acc.x = f0.x; acc.y = f0.y; acc.z = f1.x; acc.w = f1.y;
    }
    int e  = g_off[w];
    int e1 = g_off[w + 1];
    for (; e + 7 < e1; e += 8) {
        int s[8];
#pragma unroll
        for (int q = 0; q < 8; q++) s[q] = g_srcs[e + q];
        uint2 u[8];
#pragma unroll
        for (int q = 0; q < 8; q++) u[q] = hs[(size_t)s[q] * 32 + lane];
#pragma unroll
        for (int q = 0; q < 8; q++) {
            float2 f0 = __half22float2(*(__half2*)&u[q].x);
            float2 f1 = __half22float2(*(__half2*)&u[q].y);
            acc.x += f0.x; acc.y += f0.y; acc.z += f1.x; acc.w += f1.y;
        }
    }
    for (; e < e1; e++) {
        uint2 u = hs[(size_t)g_srcs[e] * 32 + lane];
        float2 f0 = __half22float2(*(__half2*)&u.x);
        float2 f1 = __half22float2(*(__half2*)&u.y);
        acc.x += f0.x; acc.y += f0.y; acc.z += f1.x; acc.w += f1.y;
    }
    float dv = g_dinv[w];
    float4 bb = ((const float4*)b1)[lane];
    float4 o;
    o.x = fmaxf(fmaf(acc.x, dv, bb.x), 0.f);
    o.y = fmaxf(fmaf(acc.y, dv, bb.y), 0.f);
    o.z = fmaxf(fmaf(acc.z, dv, bb.z), 0.f);
    o.w = fmaxf(fmaf(acc.w, dv, bb.w), 0.f);
    ((float4*)g_agg1)[(size_t)w * 32 + lane] = o;
}

// layer 2: fp32 table, width 64 (float2 per lane), +bias, writes d_out
__global__ void k_agg2(const float* __restrict__ b2, float* __restrict__ out) {
    int w    = (blockIdx.x * blockDim.x + threadIdx.x) >> 5;
    int lane = threadIdx.x & 31;
    if (w >= N_NODES) return;
    const float2* hs = (const float2*)g_hs2;
    float2 acc = hs[(size_t)w * 32 + lane];
    int e  = g_off[w];
    int e1 = g_off[w + 1];
    for (; e + 7 < e1; e += 8) {
        int s[8];
#pragma unroll
        for (int q = 0; q < 8; q++) s[q] = g_srcs[e + q];
        float2 v[8];
#pragma unroll
        for (int q = 0; q < 8; q++) v[q] = hs[(size_t)s[q] * 32 + lane];
#pragma unroll
        for (int q = 0; q < 8; q++) { acc.x += v[q].x; acc.y += v[q].y; }
    }
    for (; e < e1; e++) {
        float2 v = hs[(size_t)g_srcs[e] * 32 + lane];
        acc.x += v.x; acc.y += v.y;
    }
    float dv = g_dinv[w];
    float2 bb = ((const float2*)b2)[lane];
    float2 o;
    o.x = fmaf(acc.x, dv, bb.x);
    o.y = fmaf(acc.y, dv, bb.y);
    ((float2*)out)[(size_t)w * 32 + lane] = o;
}

// ================= launcher (k_mma1 at submission index 3 for ncu) =================
extern "C" void kernel_launch(void* const* d_in, const int* in_sizes, int n_in,
                              void* d_out, int out_size) {
    const float* x  = (const float*)d_in[0];
    const int*   ei = (const int*)d_in[1];
    const float* W1 = (const float*)d_in[2];
    const float* b1 = (const float*)d_in[3];
    const float* W2 = (const float*)d_in[4];
    const float* b2 = (const float*)d_in[5];
    float* out = (float*)d_out;

    const int NB_E4 = (N_EDGES / 4 + 255) / 256;
    const int NB_G  = (N_NODES + 127) / 128;   // 782

    k_init     <<<(INIT_TOTAL + 255) / 256, 256>>>(W1);       // 0
    k_hist     <<<NB_E4, 256>>>(ei);                          // 1
    k_scan_all <<<1, 1024>>>();                               // 2
    k_mma1     <<<NB_G, 256, SMEM_G1>>>(x);                   // 3 <- ncu slot
    k_fill     <<<NB_E4, 256>>>(ei);                          // 4
    k_agg1     <<<(N_NODES + 7) / 8, 256>>>(b1);              // 5
    k_gemm2    <<<NB_G, 256>>>(W2);                           // 6
    k_agg2     <<<(N_NODES + 7) / 8, 256>>>(b2, out);         // 7
}